// round 3
// baseline (speedup 1.0000x reference)
#include <cuda_runtime.h>
#include <math.h>
#include <float.h>
#include <stdint.h>

#define BB      64
#define TT      100
#define NN      20000
#define NCH     32
#define CHUNK_REAL 625
#define CHUNK_PAD  640
#define NPAIR   (CHUNK_PAD / 2)       // 320 pairs per CTA
#define WARPS   4
#define SUBPAIR (NPAIR / WARPS)       // 80 pairs per warp (160 points)
#define SEGPAIR 8                     // pairs per segment (16 points)
#define NSEG    (SUBPAIR / SEGPAIR)   // 10
#define NSUB    (NCH * WARPS)         // 128 partials per (b,t)
#define THREADS 128

// Scratch (no allocation allowed in kernel_launch)
__device__ float g_pmin[BB * NSUB * TT];
__device__ int   g_pidx[BB * NSUB * TT];
__device__ float g_persum[BB];

// ---- packed f32x2 helpers -------------------------------------------------
__device__ __forceinline__ uint64_t ffma2(uint64_t a, uint64_t b, uint64_t c) {
    uint64_t d;
    asm("fma.rn.f32x2 %0, %1, %2, %3;" : "=l"(d) : "l"(a), "l"(b), "l"(c));
    return d;
}
__device__ __forceinline__ uint64_t pack2(float v) {
    uint64_t r;
    asm("mov.b64 %0, {%1, %1};" : "=l"(r) : "f"(v));
    return r;
}
__device__ __forceinline__ void unpack2(float& lo, float& hi, uint64_t v) {
    asm("mov.b64 {%0, %1}, %2;" : "=f"(lo), "=f"(hi) : "l"(v));
}
__device__ __forceinline__ void lds_v2b64(uint64_t& a, uint64_t& b, uint32_t addr) {
    asm volatile("ld.shared.v2.b64 {%0, %1}, [%2];" : "=l"(a), "=l"(b) : "r"(addr));
}
__device__ __forceinline__ uint32_t smem_u32(const void* p) {
    uint32_t a;
    asm("{ .reg .u64 t; cvta.to.shared.u64 t, %1; cvt.u32.u64 %0, t; }"
        : "=r"(a) : "l"(p));
    return a;
}

// ---------------------------------------------------------------------------
// Kernel 1: CTA = (chunk, b). Transform 625-pt chunk into local frame once,
// store pair-interleaved in SMEM: pair m = [x0,x1, y0,y1, z0,z1, c0,c1]
// (c = 0.5*|p|^2). Each warp scans 80 pairs for 4 waypoints/lane using packed
// FFMA2 (2 points / 3 FFMA per chain) + scalar FMNMX on the register halves.
// Segment-level value min (16 pts) + exact-equality rescan recovers the index.
// ---------------------------------------------------------------------------
__global__ void __launch_bounds__(THREADS, 8) nn_kernel(
    const float* __restrict__ poses,     // [B,4,4] row-major
    const float* __restrict__ wpts,      // [B,T,3]
    const float* __restrict__ boundary)  // [4,N]
{
    __shared__ uint64_t pts[NPAIR * 4];  // 10240 B

    const int ch  = blockIdx.x;
    const int b   = blockIdx.y;
    const int tid = threadIdx.x;

    // SE(3) inverse: p_local = R^T (p_global - t)
    const float* P = poses + b * 16;
    const float r00 = P[0], r01 = P[1], r02 = P[2],  tx = P[3];
    const float r10 = P[4], r11 = P[5], r12 = P[6],  ty = P[7];
    const float r20 = P[8], r21 = P[9], r22 = P[10], tz = P[11];

    const int gbase = ch * CHUNK_REAL;
    float* fpts = (float*)pts;
    #pragma unroll
    for (int i = tid; i < CHUNK_PAD; i += THREADS) {
        float lx = 0.0f, ly = 0.0f, lz = 0.0f, c = 1e30f;  // pad: never wins
        if (i < CHUNK_REAL) {
            float px = boundary[0 * NN + gbase + i];
            float py = boundary[1 * NN + gbase + i];
            float pz = boundary[2 * NN + gbase + i];
            float dx = px - tx, dy = py - ty, dz = pz - tz;
            lx = fmaf(r00, dx, fmaf(r10, dy, r20 * dz));
            ly = fmaf(r01, dx, fmaf(r11, dy, r21 * dz));
            lz = fmaf(r02, dx, fmaf(r12, dy, r22 * dz));
            c  = 0.5f * fmaf(lx, lx, fmaf(ly, ly, lz * lz));
        }
        int m = i >> 1, h = i & 1;
        fpts[m * 8 + 0 + h] = lx;
        fpts[m * 8 + 2 + h] = ly;
        fpts[m * 8 + 4 + h] = lz;
        fpts[m * 8 + 6 + h] = c;
    }
    __syncthreads();

    const int warp = tid >> 5;
    const int lane = tid & 31;

    // 4 waypoint slots per lane (slots >= TT duplicate t=TT-1, never stored)
    uint64_t nwx2[4], nwy2[4], nwz2[4];
    int slot[4];
    #pragma unroll
    for (int j = 0; j < 4; ++j) {
        slot[j] = lane + 32 * j;
        int t = (slot[j] < TT) ? slot[j] : (TT - 1);
        const float* w = wpts + (b * TT + t) * 3;
        nwx2[j] = pack2(-w[0]);
        nwy2[j] = pack2(-w[1]);
        nwz2[j] = pack2(-w[2]);
    }

    float best[4];
    int   sid[4];
    #pragma unroll
    for (int j = 0; j < 4; ++j) { best[j] = FLT_MAX; sid[j] = 0; }

    const uint32_t wbase = smem_u32(pts) + (uint32_t)(warp * SUBPAIR) * 32u;

    for (int s = 0; s < NSEG; ++s) {
        const uint32_t segb = wbase + (uint32_t)(s * SEGPAIR) * 32u;
        float sv[4];
        #pragma unroll
        for (int j = 0; j < 4; ++j) sv[j] = FLT_MAX;

        #pragma unroll 2
        for (int pp = 0; pp < SEGPAIR; ++pp) {
            uint64_t xx, yy, zz, cc;
            lds_v2b64(xx, yy, segb + pp * 32u);        // broadcast, conflict-free
            lds_v2b64(zz, cc, segb + pp * 32u + 16u);
            #pragma unroll
            for (int j = 0; j < 4; ++j) {
                uint64_t q = ffma2(nwx2[j], xx,
                             ffma2(nwy2[j], yy,
                             ffma2(nwz2[j], zz, cc)));
                float qlo, qhi;
                unpack2(qlo, qhi, q);                  // register alias, free
                sv[j] = fminf(sv[j], fminf(qlo, qhi));
            }
        }
        #pragma unroll
        for (int j = 0; j < 4; ++j) {
            sid[j]  = (sv[j] < best[j]) ? s : sid[j];
            best[j] = fminf(best[j], sv[j]);
        }
    }

    // Rescan winning 16-pt segment; scalar fmaf chain matches the per-element
    // semantics of fma.rn.f32x2 exactly, so equality recovery is exact.
    const float* f = (const float*)pts;
    #pragma unroll
    for (int j = 0; j < 4; ++j) {
        float nwx, nwy, nwz, dmy;
        unpack2(nwx, dmy, nwx2[j]);
        unpack2(nwy, dmy, nwy2[j]);
        unpack2(nwz, dmy, nwz2[j]);
        const int pbase = warp * SUBPAIR * 2 + sid[j] * SEGPAIR * 2;
        int loc = -1;
        #pragma unroll
        for (int k = 0; k < SEGPAIR * 2; ++k) {
            int p = pbase + k, m = p >> 1, h = p & 1;
            float q = fmaf(nwx, f[m * 8 + 0 + h],
                      fmaf(nwy, f[m * 8 + 2 + h],
                      fmaf(nwz, f[m * 8 + 4 + h], f[m * 8 + 6 + h])));
            if (q == best[j] && loc < 0) loc = k;
        }
        if (loc < 0) loc = 0;  // unreachable safety
        if (slot[j] < TT) {
            const int sub = ch * WARPS + warp;
            const int o   = (b * NSUB + sub) * TT + slot[j];   // coalesced
            g_pmin[o] = best[j];
            g_pidx[o] = gbase + pbase + loc;
        }
    }
}

// ---------------------------------------------------------------------------
// Kernel 2: per-b block. Reduce NSUB partials per waypoint (coalesced layout,
// strict < keeps lowest sub = lowest global index), fetch winner, transform,
// dot with transformed normal, ExpRelu, block-sum over T.
// ---------------------------------------------------------------------------
__global__ void __launch_bounds__(128) finish_kernel(
    const float* __restrict__ poses,
    const float* __restrict__ wpts,
    const float* __restrict__ boundary,
    const float* __restrict__ nrms)      // [3,N]
{
    const int b = blockIdx.x;
    const int t = threadIdx.x;

    float val = 0.0f;
    if (t < TT) {
        const float* pm = g_pmin + b * NSUB * TT + t;
        const int*   pi = g_pidx + b * NSUB * TT + t;
        float bq = pm[0];
        int   bn = pi[0];
        #pragma unroll 8
        for (int s = 1; s < NSUB; ++s) {
            float q = pm[s * TT];
            int   i = pi[s * TT];
            if (q < bq) { bq = q; bn = i; }
        }

        const float* P = poses + b * 16;
        const float r00 = P[0], r01 = P[1], r02 = P[2],  tx = P[3];
        const float r10 = P[4], r11 = P[5], r12 = P[6],  ty = P[7];
        const float r20 = P[8], r21 = P[9], r22 = P[10], tz = P[11];

        float px = boundary[0 * NN + bn];
        float py = boundary[1 * NN + bn];
        float pz = boundary[2 * NN + bn];
        float dx = px - tx, dy = py - ty, dz = pz - tz;
        float cpx = fmaf(r00, dx, fmaf(r10, dy, r20 * dz));
        float cpy = fmaf(r01, dx, fmaf(r11, dy, r21 * dz));
        float cpz = fmaf(r02, dx, fmaf(r12, dy, r22 * dz));

        float nx = nrms[0 * NN + bn];
        float ny = nrms[1 * NN + bn];
        float nz = nrms[2 * NN + bn];
        float cnx = fmaf(r00, nx, fmaf(r10, ny, r20 * nz));
        float cny = fmaf(r01, nx, fmaf(r11, ny, r21 * nz));
        float cnz = fmaf(r02, nx, fmaf(r12, ny, r22 * nz));

        const float* w = wpts + (b * TT + t) * 3;
        float d = (w[0] - cpx) * cnx + (w[1] - cpy) * cny + (w[2] - cpz) * cnz;

        val = (d > 0.0f) ? (d + 1.0f) : expf(0.5f * d);  // ExpRelu a=1, b=0.5
    }

    __shared__ float sh[128];
    sh[t] = val;
    __syncthreads();
    #pragma unroll
    for (int s = 64; s > 0; s >>= 1) {
        if (t < s) sh[t] += sh[t + s];
        __syncthreads();
    }
    if (t == 0) g_persum[b] = sh[0];
}

// ---------------------------------------------------------------------------
// Kernel 3: one warp sums the 64 per-b sums -> scalar loss. Deterministic.
// ---------------------------------------------------------------------------
__global__ void final_kernel(float* __restrict__ out)
{
    const int i = threadIdx.x;  // 32 threads
    float s = g_persum[i] + g_persum[i + 32];
    #pragma unroll
    for (int o = 16; o > 0; o >>= 1)
        s += __shfl_down_sync(0xFFFFFFFFu, s, o);
    if (i == 0) out[0] = s * (1.0f / (float)(BB * TT));
}

// ---------------------------------------------------------------------------
extern "C" void kernel_launch(void* const* d_in, const int* in_sizes, int n_in,
                              void* d_out, int out_size)
{
    const float* poses    = (const float*)d_in[0];  // [64,4,4]
    const float* wpts     = (const float*)d_in[1];  // [64,100,3]
    const float* boundary = (const float*)d_in[2];  // [4,20000]
    const float* nrms     = (const float*)d_in[3];  // [3,20000]
    float* out = (float*)d_out;

    dim3 grid1(NCH, BB);
    nn_kernel<<<grid1, THREADS>>>(poses, wpts, boundary);
    finish_kernel<<<BB, 128>>>(poses, wpts, boundary, nrms);
    final_kernel<<<1, 32>>>(out);
}

// round 4
// speedup vs baseline: 1.0083x; 1.0083x over previous
#include <cuda_runtime.h>
#include <math.h>
#include <float.h>
#include <stdint.h>

#define BB      64
#define TT      100
#define NN      20000
#define NCH     32
#define CHUNK_REAL 625
#define CHUNK_PAD  640
#define NPAIR   (CHUNK_PAD / 2)       // 320 pairs per CTA
#define WARPS   4
#define SUBPAIR (NPAIR / WARPS)       // 80 pairs per warp (160 points)
#define SEGPAIR 8                     // pairs per segment (16 points)
#define NSEG    (SUBPAIR / SEGPAIR)   // 10
#define NSUB    (NCH * WARPS)         // 128 partials per (b,t)
#define THREADS 128

// Scratch (no allocation allowed in kernel_launch)
__device__ float g_pmin[BB * NSUB * TT];
__device__ int   g_pidx[BB * NSUB * TT];
__device__ float g_persum[BB];

// ---- packed f32x2 helpers -------------------------------------------------
__device__ __forceinline__ uint64_t ffma2(uint64_t a, uint64_t b, uint64_t c) {
    uint64_t d;
    asm("fma.rn.f32x2 %0, %1, %2, %3;" : "=l"(d) : "l"(a), "l"(b), "l"(c));
    return d;
}
__device__ __forceinline__ uint64_t pack2(float v) {
    uint64_t r;
    asm("mov.b64 %0, {%1, %1};" : "=l"(r) : "f"(v));
    return r;
}
__device__ __forceinline__ void unpack2(float& lo, float& hi, uint64_t v) {
    asm("mov.b64 {%0, %1}, %2;" : "=f"(lo), "=f"(hi) : "l"(v));
}
__device__ __forceinline__ void lds_v2b64(uint64_t& a, uint64_t& b, uint32_t addr) {
    asm volatile("ld.shared.v2.b64 {%0, %1}, [%2];" : "=l"(a), "=l"(b) : "r"(addr));
}
__device__ __forceinline__ uint32_t smem_u32(const void* p) {
    uint32_t a;
    asm("{ .reg .u64 t; cvta.to.shared.u64 t, %1; cvt.u32.u64 %0, t; }"
        : "=r"(a) : "l"(p));
    return a;
}

// ---------------------------------------------------------------------------
// Kernel 1: CTA = (chunk, b). Transform 625-pt chunk into local frame once,
// store pair-interleaved in SMEM: pair m = [x0,x1, y0,y1, z0,z1, c0,c1]
// (c = 0.5*|p|^2). Each warp scans 80 pairs for 4 waypoints/lane using packed
// FFMA2 (2 points / 3 FFMA per chain) + scalar FMNMX on the register halves.
// Segment-level value min (16 pts) + exact-equality rescan recovers the index.
// ---------------------------------------------------------------------------
__global__ void __launch_bounds__(THREADS, 8) nn_kernel(
    const float* __restrict__ poses,     // [B,4,4] row-major
    const float* __restrict__ wpts,      // [B,T,3]
    const float* __restrict__ boundary)  // [4,N]
{
    __shared__ uint64_t pts[NPAIR * 4];  // 10240 B

    const int ch  = blockIdx.x;
    const int b   = blockIdx.y;
    const int tid = threadIdx.x;

    // SE(3) inverse: p_local = R^T (p_global - t)
    const float* P = poses + b * 16;
    const float r00 = P[0], r01 = P[1], r02 = P[2],  tx = P[3];
    const float r10 = P[4], r11 = P[5], r12 = P[6],  ty = P[7];
    const float r20 = P[8], r21 = P[9], r22 = P[10], tz = P[11];

    const int gbase = ch * CHUNK_REAL;
    float* fpts = (float*)pts;
    #pragma unroll
    for (int i = tid; i < CHUNK_PAD; i += THREADS) {
        float lx = 0.0f, ly = 0.0f, lz = 0.0f, c = 1e30f;  // pad: never wins
        if (i < CHUNK_REAL) {
            float px = boundary[0 * NN + gbase + i];
            float py = boundary[1 * NN + gbase + i];
            float pz = boundary[2 * NN + gbase + i];
            float dx = px - tx, dy = py - ty, dz = pz - tz;
            lx = fmaf(r00, dx, fmaf(r10, dy, r20 * dz));
            ly = fmaf(r01, dx, fmaf(r11, dy, r21 * dz));
            lz = fmaf(r02, dx, fmaf(r12, dy, r22 * dz));
            c  = 0.5f * fmaf(lx, lx, fmaf(ly, ly, lz * lz));
        }
        int m = i >> 1, h = i & 1;
        fpts[m * 8 + 0 + h] = lx;
        fpts[m * 8 + 2 + h] = ly;
        fpts[m * 8 + 4 + h] = lz;
        fpts[m * 8 + 6 + h] = c;
    }
    __syncthreads();

    const int warp = tid >> 5;
    const int lane = tid & 31;

    // 4 waypoint slots per lane (slots >= TT duplicate t=TT-1, never stored)
    uint64_t nwx2[4], nwy2[4], nwz2[4];
    int slot[4];
    #pragma unroll
    for (int j = 0; j < 4; ++j) {
        slot[j] = lane + 32 * j;
        int t = (slot[j] < TT) ? slot[j] : (TT - 1);
        const float* w = wpts + (b * TT + t) * 3;
        nwx2[j] = pack2(-w[0]);
        nwy2[j] = pack2(-w[1]);
        nwz2[j] = pack2(-w[2]);
    }

    float best[4];
    int   sid[4];
    #pragma unroll
    for (int j = 0; j < 4; ++j) { best[j] = FLT_MAX; sid[j] = 0; }

    const uint32_t wbase = smem_u32(pts) + (uint32_t)(warp * SUBPAIR) * 32u;

    for (int s = 0; s < NSEG; ++s) {
        const uint32_t segb = wbase + (uint32_t)(s * SEGPAIR) * 32u;
        float sv[4];
        #pragma unroll
        for (int j = 0; j < 4; ++j) sv[j] = FLT_MAX;

        #pragma unroll 2
        for (int pp = 0; pp < SEGPAIR; ++pp) {
            uint64_t xx, yy, zz, cc;
            lds_v2b64(xx, yy, segb + pp * 32u);        // broadcast, conflict-free
            lds_v2b64(zz, cc, segb + pp * 32u + 16u);
            #pragma unroll
            for (int j = 0; j < 4; ++j) {
                uint64_t q = ffma2(nwx2[j], xx,
                             ffma2(nwy2[j], yy,
                             ffma2(nwz2[j], zz, cc)));
                float qlo, qhi;
                unpack2(qlo, qhi, q);                  // register alias, free
                sv[j] = fminf(sv[j], fminf(qlo, qhi));
            }
        }
        #pragma unroll
        for (int j = 0; j < 4; ++j) {
            sid[j]  = (sv[j] < best[j]) ? s : sid[j];
            best[j] = fminf(best[j], sv[j]);
        }
    }

    // Rescan winning 16-pt segment; scalar fmaf chain matches the per-element
    // semantics of fma.rn.f32x2 exactly, so equality recovery is exact.
    const float* f = (const float*)pts;
    #pragma unroll
    for (int j = 0; j < 4; ++j) {
        float nwx, nwy, nwz, dmy;
        unpack2(nwx, dmy, nwx2[j]);
        unpack2(nwy, dmy, nwy2[j]);
        unpack2(nwz, dmy, nwz2[j]);
        const int pbase = warp * SUBPAIR * 2 + sid[j] * SEGPAIR * 2;
        int loc = -1;
        #pragma unroll
        for (int k = 0; k < SEGPAIR * 2; ++k) {
            int p = pbase + k, m = p >> 1, h = p & 1;
            float q = fmaf(nwx, f[m * 8 + 0 + h],
                      fmaf(nwy, f[m * 8 + 2 + h],
                      fmaf(nwz, f[m * 8 + 4 + h], f[m * 8 + 6 + h])));
            if (q == best[j] && loc < 0) loc = k;
        }
        if (loc < 0) loc = 0;  // unreachable safety
        if (slot[j] < TT) {
            const int sub = ch * WARPS + warp;
            const int o   = (b * NSUB + sub) * TT + slot[j];   // coalesced
            g_pmin[o] = best[j];
            g_pidx[o] = gbase + pbase + loc;
        }
    }
}

// ---------------------------------------------------------------------------
// Kernel 2: per-b block. Reduce NSUB partials per waypoint (coalesced layout,
// strict < keeps lowest sub = lowest global index), fetch winner, transform,
// dot with transformed normal, ExpRelu, block-sum over T.
// ---------------------------------------------------------------------------
__global__ void __launch_bounds__(128) finish_kernel(
    const float* __restrict__ poses,
    const float* __restrict__ wpts,
    const float* __restrict__ boundary,
    const float* __restrict__ nrms)      // [3,N]
{
    const int b = blockIdx.x;
    const int t = threadIdx.x;

    float val = 0.0f;
    if (t < TT) {
        const float* pm = g_pmin + b * NSUB * TT + t;
        const int*   pi = g_pidx + b * NSUB * TT + t;
        float bq = pm[0];
        int   bn = pi[0];
        #pragma unroll 8
        for (int s = 1; s < NSUB; ++s) {
            float q = pm[s * TT];
            int   i = pi[s * TT];
            if (q < bq) { bq = q; bn = i; }
        }

        const float* P = poses + b * 16;
        const float r00 = P[0], r01 = P[1], r02 = P[2],  tx = P[3];
        const float r10 = P[4], r11 = P[5], r12 = P[6],  ty = P[7];
        const float r20 = P[8], r21 = P[9], r22 = P[10], tz = P[11];

        float px = boundary[0 * NN + bn];
        float py = boundary[1 * NN + bn];
        float pz = boundary[2 * NN + bn];
        float dx = px - tx, dy = py - ty, dz = pz - tz;
        float cpx = fmaf(r00, dx, fmaf(r10, dy, r20 * dz));
        float cpy = fmaf(r01, dx, fmaf(r11, dy, r21 * dz));
        float cpz = fmaf(r02, dx, fmaf(r12, dy, r22 * dz));

        float nx = nrms[0 * NN + bn];
        float ny = nrms[1 * NN + bn];
        float nz = nrms[2 * NN + bn];
        float cnx = fmaf(r00, nx, fmaf(r10, ny, r20 * nz));
        float cny = fmaf(r01, nx, fmaf(r11, ny, r21 * nz));
        float cnz = fmaf(r02, nx, fmaf(r12, ny, r22 * nz));

        const float* w = wpts + (b * TT + t) * 3;
        float d = (w[0] - cpx) * cnx + (w[1] - cpy) * cny + (w[2] - cpz) * cnz;

        val = (d > 0.0f) ? (d + 1.0f) : expf(0.5f * d);  // ExpRelu a=1, b=0.5
    }

    __shared__ float sh[128];
    sh[t] = val;
    __syncthreads();
    #pragma unroll
    for (int s = 64; s > 0; s >>= 1) {
        if (t < s) sh[t] += sh[t + s];
        __syncthreads();
    }
    if (t == 0) g_persum[b] = sh[0];
}

// ---------------------------------------------------------------------------
// Kernel 3: one warp sums the 64 per-b sums -> scalar loss. Deterministic.
// ---------------------------------------------------------------------------
__global__ void final_kernel(float* __restrict__ out)
{
    const int i = threadIdx.x;  // 32 threads
    float s = g_persum[i] + g_persum[i + 32];
    #pragma unroll
    for (int o = 16; o > 0; o >>= 1)
        s += __shfl_down_sync(0xFFFFFFFFu, s, o);
    if (i == 0) out[0] = s * (1.0f / (float)(BB * TT));
}

// ---------------------------------------------------------------------------
extern "C" void kernel_launch(void* const* d_in, const int* in_sizes, int n_in,
                              void* d_out, int out_size)
{
    const float* poses    = (const float*)d_in[0];  // [64,4,4]
    const float* wpts     = (const float*)d_in[1];  // [64,100,3]
    const float* boundary = (const float*)d_in[2];  // [4,20000]
    const float* nrms     = (const float*)d_in[3];  // [3,20000]
    float* out = (float*)d_out;

    dim3 grid1(NCH, BB);
    nn_kernel<<<grid1, THREADS>>>(poses, wpts, boundary);
    finish_kernel<<<BB, 128>>>(poses, wpts, boundary, nrms);
    final_kernel<<<1, 32>>>(out);
}